// round 5
// baseline (speedup 1.0000x reference)
#include <cuda_runtime.h>
#include <cuda_fp16.h>
#include <math.h>
#include <stdint.h>

// Problem constants
#define T_DIM 32768
#define H_DIM 1024
#define V_DIM 32
#define D_DIM 1024

// GEMM tiling
#define BM 128
#define BN 256
#define BK 32                      // fp16 K elements per chunk (64 B/row)
#define NCHUNK (H_DIM / BK)        // 32
#define RSTRIDE 80                 // padded smem row stride
#define OFF_A 0
#define OFF_B (BM * RSTRIDE)                     // A: 10240 B
#define STAGE_BYTES ((BM + BN) * RSTRIDE)        // 30720
#define GEMM_SMEM (4 * STAGE_BYTES)              // 122880

// ---------------------------------------------------------------------------
// Device scratch
// ---------------------------------------------------------------------------
__device__ int g_tok[T_DIM];
__device__ int g_run_first[T_DIM + 1];
__device__ int g_row_start[T_DIM];
__device__ int g_row_count[T_DIM];
__device__ int g_nseg;
__device__ int g_nvalid;
__device__ __align__(16) __half g_C_h[(size_t)T_DIM * H_DIM];  // 64 MB
__device__ __align__(16) __half g_W_h[(size_t)D_DIM * H_DIM];  // 2 MB

__device__ __forceinline__ uint32_t smem_to_u32(const void* p) {
    uint32_t a;
    asm("{ .reg .u64 t; cvta.to.shared.u64 t, %1; cvt.u32.u64 %0, t; }" : "=r"(a) : "l"(p));
    return a;
}

// ---------------------------------------------------------------------------
// Arch-neutral async-copy / mma helpers (sm_80+ PTX, legal on sm_100 target)
// ---------------------------------------------------------------------------
__device__ __forceinline__ void cp16(uint32_t dst, const void* src) {
    asm volatile("cp.async.cg.shared.global [%0], [%1], 16;" :: "r"(dst), "l"(src));
}
#define CP_COMMIT() asm volatile("cp.async.commit_group;" ::: "memory")
#define CP_WAIT2()  asm volatile("cp.async.wait_group 2;" ::: "memory")

__device__ __forceinline__ void ldsm4(uint32_t a, uint32_t& r0, uint32_t& r1,
                                      uint32_t& r2, uint32_t& r3) {
    asm volatile("ldmatrix.sync.aligned.m8n8.x4.shared.b16 {%0,%1,%2,%3}, [%4];"
                 : "=r"(r0), "=r"(r1), "=r"(r2), "=r"(r3) : "r"(a));
}
__device__ __forceinline__ void mma16816(float* c, const uint32_t* a, const uint32_t* b) {
    asm volatile("mma.sync.aligned.m16n8k16.row.col.f32.f16.f16.f32 "
                 "{%0,%1,%2,%3}, {%4,%5,%6,%7}, {%8,%9}, {%0,%1,%2,%3};"
                 : "+f"(c[0]), "+f"(c[1]), "+f"(c[2]), "+f"(c[3])
                 : "r"(a[0]), "r"(a[1]), "r"(a[2]), "r"(a[3]), "r"(b[0]), "r"(b[1]));
}

// ---------------------------------------------------------------------------
// Kernel 1: per-token argmax over V=32 logits (first-max tie rule)
// ---------------------------------------------------------------------------
__global__ __launch_bounds__(256) void argmax_kernel(const float* __restrict__ logits) {
    int t = blockIdx.x * 256 + threadIdx.x;
    if (t >= T_DIM) return;
    const float4* p = (const float4*)(logits + (size_t)t * V_DIM);
    float best = -INFINITY;
    int bi = 0;
#pragma unroll
    for (int q = 0; q < V_DIM / 4; q++) {
        float4 v = p[q];
        int b0 = q * 4;
        if (v.x > best) { best = v.x; bi = b0 + 0; }
        if (v.y > best) { best = v.y; bi = b0 + 1; }
        if (v.z > best) { best = v.z; bi = b0 + 2; }
        if (v.w > best) { best = v.w; bi = b0 + 3; }
    }
    g_tok[t] = bi;
}

// ---------------------------------------------------------------------------
// Kernel 2: segmentation — shfl warp scans + single-warp combine
// ---------------------------------------------------------------------------
__device__ __forceinline__ int block_scan_excl(int val, int tid, int* wsum, int* total) {
    const int lane = tid & 31, w = tid >> 5;
    int incl = val;
#pragma unroll
    for (int o = 1; o < 32; o <<= 1) {
        int n = __shfl_up_sync(0xFFFFFFFFu, incl, o);
        if (lane >= o) incl += n;
    }
    if (lane == 31) wsum[w] = incl;
    __syncthreads();
    if (w == 0) {
        int s = wsum[lane];
#pragma unroll
        for (int o = 1; o < 32; o <<= 1) {
            int n = __shfl_up_sync(0xFFFFFFFFu, s, o);
            if (lane >= o) s += n;
        }
        wsum[lane] = s;
    }
    __syncthreads();
    int woff = (w == 0) ? 0 : wsum[w - 1];
    *total = wsum[31];
    int excl = woff + incl - val;
    __syncthreads();   // wsum safe for reuse
    return excl;
}

__global__ __launch_bounds__(1024) void segment_kernel() {
    __shared__ int wsum[32];
    const int tid  = threadIdx.x;
    const int CH   = T_DIM / 1024;   // 32
    const int base = tid * CH;

    // Phase A: run starts
    int prev = (base == 0) ? -1 : g_tok[base - 1];
    int cnt = 0;
    unsigned flags = 0;
#pragma unroll
    for (int i = 0; i < CH; i++) {
        int cur = g_tok[base + i];
        int st = (cur != prev) ? 1 : 0;
        flags |= ((unsigned)st) << i;
        cnt += st;
        prev = cur;
    }
    int total;
    int excl = block_scan_excl(cnt, tid, wsum, &total);
    {
        int r = excl;
#pragma unroll
        for (int i = 0; i < CH; i++)
            if ((flags >> i) & 1u) g_run_first[r++] = base + i;
    }
    const int n_seg = total;
    __syncthreads();
    if (tid == 0) {
        g_run_first[n_seg] = T_DIM;
        g_nseg = n_seg;
    }
    __syncthreads();

    // Phase B: valid (tok != 0) compaction
    int vcnt = 0;
    unsigned vflags = 0;
#pragma unroll
    for (int i = 0; i < CH; i++) {
        int sidx = base + i;
        if (sidx < n_seg) {
            int f = g_run_first[sidx];
            int v = (g_tok[f] != 0) ? 1 : 0;
            vflags |= ((unsigned)v) << i;
            vcnt += v;
        }
    }
    int vtotal;
    int vexcl = block_scan_excl(vcnt, tid, wsum, &vtotal);
    {
        int d = vexcl;
#pragma unroll
        for (int i = 0; i < CH; i++) {
            int sidx = base + i;
            if (sidx < n_seg && ((vflags >> i) & 1u)) {
                int f = g_run_first[sidx];
                g_row_start[d] = f;
                g_row_count[d] = g_run_first[sidx + 1] - f;
                d++;
            }
        }
    }
    if (tid == 0) g_nvalid = vtotal;
}

// ---------------------------------------------------------------------------
// Kernel 3: segment mean -> fp16. Warp-per-row, 8 rows per block, MLP=8.
// ---------------------------------------------------------------------------
__global__ __launch_bounds__(256) void mean_kernel(const float* __restrict__ hidden) {
    const int warp = threadIdx.x >> 5, lane = threadIdx.x & 31;
    int r = blockIdx.x * 8 + warp;
    if (r >= g_nvalid) return;
    const int start = g_row_start[r];
    const int cnt   = g_row_count[r];
    const float4* src = (const float4*)(hidden + (size_t)start * H_DIM);
    float4 a[8];
#pragma unroll
    for (int j = 0; j < 8; j++) a[j] = src[lane + j * 32];
    for (int t = 1; t < cnt; t++) {
        const float4* s2 = (const float4*)(hidden + (size_t)(start + t) * H_DIM);
#pragma unroll
        for (int j = 0; j < 8; j++) {
            float4 v = s2[lane + j * 32];
            a[j].x += v.x; a[j].y += v.y; a[j].z += v.z; a[j].w += v.w;
        }
    }
    float inv = (cnt > 1) ? (1.0f / (float)cnt) : 1.0f;
    uint2* dst = (uint2*)g_C_h + (size_t)r * (H_DIM / 4);
#pragma unroll
    for (int j = 0; j < 8; j++) {
        __half2 p0 = __floats2half2_rn(a[j].x * inv, a[j].y * inv);
        __half2 p1 = __floats2half2_rn(a[j].z * inv, a[j].w * inv);
        uint2 u;
        u.x = *(const uint32_t*)&p0;
        u.y = *(const uint32_t*)&p1;
        dst[lane + j * 32] = u;
    }
}

// ---------------------------------------------------------------------------
// Kernel 4: W -> fp16
// ---------------------------------------------------------------------------
__global__ __launch_bounds__(256) void w_half_kernel(const float* __restrict__ W) {
    size_t i = (size_t)blockIdx.x * 256 + threadIdx.x;
    float4 a = ((const float4*)W)[i];
    __half2 p0 = __floats2half2_rn(a.x, a.y);
    __half2 p1 = __floats2half2_rn(a.z, a.w);
    uint2 u;
    u.x = *(const uint32_t*)&p0;
    u.y = *(const uint32_t*)&p1;
    ((uint2*)g_W_h)[i] = u;
}

// ---------------------------------------------------------------------------
// Kernel 5: fp16 GEMM via mma.sync.m16n8k16.
// 128x256x32 CTA tile, 8 warps (2x4), 64x64 warp tile, 4-stage cp.async.
// ---------------------------------------------------------------------------
__device__ __forceinline__ void fill_stage(uint32_t sb, int m0, int n0, int chunk, int tid) {
    const int k0 = chunk * BK;
#pragma unroll
    for (int h = 0; h < 2; h++) {      // A: 128 rows x 4 segs = 512 ops
        int s2 = tid + h * 256;
        int row = s2 >> 2, seg = s2 & 3;
        cp16(sb + OFF_A + row * RSTRIDE + seg * 16,
             g_C_h + (size_t)(m0 + row) * H_DIM + k0 + seg * 8);
    }
#pragma unroll
    for (int h = 0; h < 4; h++) {      // B: 256 rows x 4 segs = 1024 ops
        int s2 = tid + h * 256;
        int row = s2 >> 2, seg = s2 & 3;
        cp16(sb + OFF_B + row * RSTRIDE + seg * 16,
             g_W_h + (size_t)(n0 + row) * H_DIM + k0 + seg * 8);
    }
}

__global__ __launch_bounds__(256, 1) void gemm_mma_kernel(const float* __restrict__ bias,
                                                          float* __restrict__ out) {
    extern __shared__ char smem[];
    const int n_valid = g_nvalid;
    const int m0 = blockIdx.y * BM;
    const int n0 = blockIdx.x * BN;
    const int tid = threadIdx.x;

    if (m0 >= n_valid) {      // fully masked: zeros
        float4 z = make_float4(0.f, 0.f, 0.f, 0.f);
        for (int i = tid; i < BM * (BN / 4); i += 256) {
            int r = i >> 6, c4 = i & 63;
            ((float4*)(out + (size_t)(m0 + r) * D_DIM + n0))[c4] = z;
        }
        return;
    }

    const int wid = tid >> 5, lane = tid & 31;
    const int warp_m = wid >> 2;   // 0..1
    const int warp_n = wid & 3;    // 0..3
    uint32_t sb = smem_to_u32(smem);

    const uint32_t a_lane = (uint32_t)((warp_m * 64 + (lane & 15)) * RSTRIDE + (lane >> 4) * 16);
    const uint32_t b_lane = (uint32_t)((warp_n * 64 + (lane & 15)) * RSTRIDE + (lane >> 4) * 16);

    float acc[4][8][4];
#pragma unroll
    for (int i = 0; i < 4; i++)
#pragma unroll
        for (int j = 0; j < 8; j++)
#pragma unroll
            for (int k = 0; k < 4; k++) acc[i][j][k] = 0.f;

    fill_stage(sb + 0 * STAGE_BYTES, m0, n0, 0, tid); CP_COMMIT();
    fill_stage(sb + 1 * STAGE_BYTES, m0, n0, 1, tid); CP_COMMIT();
    fill_stage(sb + 2 * STAGE_BYTES, m0, n0, 2, tid); CP_COMMIT();

    for (int c = 0; c < NCHUNK; c++) {
        CP_WAIT2();
        __syncthreads();
        if (c + 3 < NCHUNK) fill_stage(sb + ((c + 3) & 3) * STAGE_BYTES, m0, n0, c + 3, tid);
        CP_COMMIT();

        const uint32_t st = sb + (c & 3) * STAGE_BYTES;
#pragma unroll
        for (int ks = 0; ks < 2; ks++) {
            uint32_t ah[4][4], bh[8][2];
#pragma unroll
            for (int mi = 0; mi < 4; mi++) {
                uint32_t ad = st + OFF_A + a_lane + mi * (16 * RSTRIDE) + ks * 32;
                ldsm4(ad, ah[mi][0], ah[mi][1], ah[mi][2], ah[mi][3]);
            }
#pragma unroll
            for (int j = 0; j < 4; j++) {
                uint32_t bd = st + OFF_B + b_lane + j * (16 * RSTRIDE) + ks * 32;
                uint32_t r0, r1, r2, r3;
                ldsm4(bd, r0, r1, r2, r3);
                bh[2 * j][0] = r0; bh[2 * j + 1][0] = r1;
                bh[2 * j][1] = r2; bh[2 * j + 1][1] = r3;
            }
#pragma unroll
            for (int mi = 0; mi < 4; mi++)
#pragma unroll
                for (int ni = 0; ni < 8; ni++)
                    mma16816(acc[mi][ni], ah[mi], bh[ni]);
        }
    }

    // Epilogue: bias + row mask
    const int r_in = lane >> 2;
    const int c2 = (lane & 3) * 2;
#pragma unroll
    for (int mi = 0; mi < 4; mi++) {
#pragma unroll
        for (int half = 0; half < 2; half++) {
            int row = m0 + warp_m * 64 + mi * 16 + r_in + half * 8;
            bool rv = row < n_valid;
            float* op = out + (size_t)row * D_DIM;
#pragma unroll
            for (int ni = 0; ni < 8; ni++) {
                int col = n0 + warp_n * 64 + ni * 8 + c2;
                float2 v;
                if (rv) {
                    float2 b2 = *(const float2*)(bias + col);
                    v.x = acc[mi][ni][half * 2 + 0] + b2.x;
                    v.y = acc[mi][ni][half * 2 + 1] + b2.y;
                } else {
                    v.x = 0.f; v.y = 0.f;
                }
                *(float2*)(op + col) = v;
            }
        }
    }
}

// ---------------------------------------------------------------------------
// Launch
// ---------------------------------------------------------------------------
extern "C" void kernel_launch(void* const* d_in, const int* in_sizes, int n_in,
                              void* d_out, int out_size) {
    const float* hidden = (const float*)d_in[0];   // [1, T, H]
    const float* logits = (const float*)d_in[1];   // [1, T, V]
    const float* W      = (const float*)d_in[2];   // [D, H]
    const float* bias   = (const float*)d_in[3];   // [D]
    float* out          = (float*)d_out;           // [1, T, D]

    cudaFuncSetAttribute(gemm_mma_kernel, cudaFuncAttributeMaxDynamicSharedMemorySize,
                         GEMM_SMEM);

    w_half_kernel<<<(D_DIM * H_DIM) / (256 * 4), 256>>>(W);
    argmax_kernel<<<T_DIM / 256, 256>>>(logits);
    segment_kernel<<<1, 1024>>>();
    mean_kernel<<<T_DIM / 8, 256>>>(hidden);
    dim3 grid(D_DIM / BN, T_DIM / BM);
    gemm_mma_kernel<<<grid, 256, GEMM_SMEM>>>(bias, out);
}

// round 6
// speedup vs baseline: 1.0900x; 1.0900x over previous
#include <cuda_runtime.h>
#include <cuda_fp16.h>
#include <math.h>
#include <stdint.h>

// Problem constants
#define T_DIM 32768
#define H_DIM 1024
#define V_DIM 32
#define D_DIM 1024

// GEMM tiling
#define BM 128
#define BN 128
#define BK 64                      // fp16 K elements per chunk (128 B/row)
#define NCHUNK (H_DIM / BK)        // 16
#define RSTRIDE 144                // 128B data + 16B pad (conflict-free ldsm)
#define MAT_BYTES (128 * RSTRIDE)  // 18432
#define OFF_A 0
#define OFF_B MAT_BYTES
#define STAGE_BYTES (2 * MAT_BYTES)          // 36864
#define GEMM_SMEM (3 * STAGE_BYTES)          // 110592  (occ 2)

// ---------------------------------------------------------------------------
// Device scratch
// ---------------------------------------------------------------------------
__device__ int g_tok[T_DIM];
__device__ int g_run_first[T_DIM + 1];
__device__ int g_row_start[T_DIM];
__device__ int g_row_count[T_DIM];
__device__ int g_nseg;
__device__ int g_nvalid;
__device__ __align__(16) __half g_C_h[(size_t)T_DIM * H_DIM];  // 64 MB
__device__ __align__(16) __half g_W_h[(size_t)D_DIM * H_DIM];  // 2 MB

__device__ __forceinline__ uint32_t smem_to_u32(const void* p) {
    uint32_t a;
    asm("{ .reg .u64 t; cvta.to.shared.u64 t, %1; cvt.u32.u64 %0, t; }" : "=r"(a) : "l"(p));
    return a;
}

// ---------------------------------------------------------------------------
// Arch-neutral async-copy / mma helpers
// ---------------------------------------------------------------------------
__device__ __forceinline__ void cp16(uint32_t dst, const void* src) {
    asm volatile("cp.async.cg.shared.global [%0], [%1], 16;" :: "r"(dst), "l"(src));
}
#define CP_COMMIT() asm volatile("cp.async.commit_group;" ::: "memory")
#define CP_WAIT1()  asm volatile("cp.async.wait_group 1;" ::: "memory")

__device__ __forceinline__ void ldsm4(uint32_t a, uint32_t& r0, uint32_t& r1,
                                      uint32_t& r2, uint32_t& r3) {
    asm volatile("ldmatrix.sync.aligned.m8n8.x4.shared.b16 {%0,%1,%2,%3}, [%4];"
                 : "=r"(r0), "=r"(r1), "=r"(r2), "=r"(r3) : "r"(a));
}
__device__ __forceinline__ void mma16816(float* c, const uint32_t* a, const uint32_t* b) {
    asm volatile("mma.sync.aligned.m16n8k16.row.col.f32.f16.f16.f32 "
                 "{%0,%1,%2,%3}, {%4,%5,%6,%7}, {%8,%9}, {%0,%1,%2,%3};"
                 : "+f"(c[0]), "+f"(c[1]), "+f"(c[2]), "+f"(c[3])
                 : "r"(a[0]), "r"(a[1]), "r"(a[2]), "r"(a[3]), "r"(b[0]), "r"(b[1]));
}

// ---------------------------------------------------------------------------
// Kernel 1: per-token argmax over V=32 logits (first-max tie rule)
// ---------------------------------------------------------------------------
__global__ __launch_bounds__(256) void argmax_kernel(const float* __restrict__ logits) {
    int t = blockIdx.x * 256 + threadIdx.x;
    if (t >= T_DIM) return;
    const float4* p = (const float4*)(logits + (size_t)t * V_DIM);
    float best = -INFINITY;
    int bi = 0;
#pragma unroll
    for (int q = 0; q < V_DIM / 4; q++) {
        float4 v = p[q];
        int b0 = q * 4;
        if (v.x > best) { best = v.x; bi = b0 + 0; }
        if (v.y > best) { best = v.y; bi = b0 + 1; }
        if (v.z > best) { best = v.z; bi = b0 + 2; }
        if (v.w > best) { best = v.w; bi = b0 + 3; }
    }
    g_tok[t] = bi;
}

// ---------------------------------------------------------------------------
// Kernel 2: segmentation — shfl warp scans + single-warp combine
// ---------------------------------------------------------------------------
__device__ __forceinline__ int block_scan_excl(int val, int tid, int* wsum, int* total) {
    const int lane = tid & 31, w = tid >> 5;
    int incl = val;
#pragma unroll
    for (int o = 1; o < 32; o <<= 1) {
        int n = __shfl_up_sync(0xFFFFFFFFu, incl, o);
        if (lane >= o) incl += n;
    }
    if (lane == 31) wsum[w] = incl;
    __syncthreads();
    if (w == 0) {
        int s = wsum[lane];
#pragma unroll
        for (int o = 1; o < 32; o <<= 1) {
            int n = __shfl_up_sync(0xFFFFFFFFu, s, o);
            if (lane >= o) s += n;
        }
        wsum[lane] = s;
    }
    __syncthreads();
    int woff = (w == 0) ? 0 : wsum[w - 1];
    *total = wsum[31];
    int excl = woff + incl - val;
    __syncthreads();
    return excl;
}

__global__ __launch_bounds__(1024) void segment_kernel() {
    __shared__ int wsum[32];
    const int tid  = threadIdx.x;
    const int CH   = T_DIM / 1024;   // 32
    const int base = tid * CH;

    int prev = (base == 0) ? -1 : g_tok[base - 1];
    int cnt = 0;
    unsigned flags = 0;
#pragma unroll
    for (int i = 0; i < CH; i++) {
        int cur = g_tok[base + i];
        int st = (cur != prev) ? 1 : 0;
        flags |= ((unsigned)st) << i;
        cnt += st;
        prev = cur;
    }
    int total;
    int excl = block_scan_excl(cnt, tid, wsum, &total);
    {
        int r = excl;
#pragma unroll
        for (int i = 0; i < CH; i++)
            if ((flags >> i) & 1u) g_run_first[r++] = base + i;
    }
    const int n_seg = total;
    __syncthreads();
    if (tid == 0) {
        g_run_first[n_seg] = T_DIM;
        g_nseg = n_seg;
    }
    __syncthreads();

    int vcnt = 0;
    unsigned vflags = 0;
#pragma unroll
    for (int i = 0; i < CH; i++) {
        int sidx = base + i;
        if (sidx < n_seg) {
            int f = g_run_first[sidx];
            int v = (g_tok[f] != 0) ? 1 : 0;
            vflags |= ((unsigned)v) << i;
            vcnt += v;
        }
    }
    int vtotal;
    int vexcl = block_scan_excl(vcnt, tid, wsum, &vtotal);
    {
        int d = vexcl;
#pragma unroll
        for (int i = 0; i < CH; i++) {
            int sidx = base + i;
            if (sidx < n_seg && ((vflags >> i) & 1u)) {
                int f = g_run_first[sidx];
                g_row_start[d] = f;
                g_row_count[d] = g_run_first[sidx + 1] - f;
                d++;
            }
        }
    }
    if (tid == 0) g_nvalid = vtotal;
}

// ---------------------------------------------------------------------------
// Kernel 3: segment mean -> fp16. Warp-per-row, 8 rows per block, MLP=8.
// ---------------------------------------------------------------------------
__global__ __launch_bounds__(256) void mean_kernel(const float* __restrict__ hidden) {
    const int warp = threadIdx.x >> 5, lane = threadIdx.x & 31;
    int r = blockIdx.x * 8 + warp;
    if (r >= g_nvalid) return;
    const int start = g_row_start[r];
    const int cnt   = g_row_count[r];
    const float4* src = (const float4*)(hidden + (size_t)start * H_DIM);
    float4 a[8];
#pragma unroll
    for (int j = 0; j < 8; j++) a[j] = src[lane + j * 32];
    for (int t = 1; t < cnt; t++) {
        const float4* s2 = (const float4*)(hidden + (size_t)(start + t) * H_DIM);
#pragma unroll
        for (int j = 0; j < 8; j++) {
            float4 v = s2[lane + j * 32];
            a[j].x += v.x; a[j].y += v.y; a[j].z += v.z; a[j].w += v.w;
        }
    }
    float inv = (cnt > 1) ? (1.0f / (float)cnt) : 1.0f;
    uint2* dst = (uint2*)g_C_h + (size_t)r * (H_DIM / 4);
#pragma unroll
    for (int j = 0; j < 8; j++) {
        __half2 p0 = __floats2half2_rn(a[j].x * inv, a[j].y * inv);
        __half2 p1 = __floats2half2_rn(a[j].z * inv, a[j].w * inv);
        uint2 u;
        u.x = *(const uint32_t*)&p0;
        u.y = *(const uint32_t*)&p1;
        dst[lane + j * 32] = u;
    }
}

// ---------------------------------------------------------------------------
// Kernel 4: W -> fp16
// ---------------------------------------------------------------------------
__global__ __launch_bounds__(256) void w_half_kernel(const float* __restrict__ W) {
    size_t i = (size_t)blockIdx.x * 256 + threadIdx.x;
    float4 a = ((const float4*)W)[i];
    __half2 p0 = __floats2half2_rn(a.x, a.y);
    __half2 p1 = __floats2half2_rn(a.z, a.w);
    uint2 u;
    u.x = *(const uint32_t*)&p0;
    u.y = *(const uint32_t*)&p1;
    ((uint2*)g_W_h)[i] = u;
}

// ---------------------------------------------------------------------------
// Kernel 5: fp16 GEMM via mma.sync.m16n8k16.
// 128x128x64 CTA tile, 8 warps (2x4), 64x32 warp tile, 3-stage cp.async, occ 2.
// ---------------------------------------------------------------------------
__device__ __forceinline__ void fill_stage(uint32_t sb, int m0, int n0, int chunk, int tid) {
    const int k0 = chunk * BK;
#pragma unroll
    for (int h = 0; h < 4; h++) {      // A: 128 rows x 8 segs = 1024 ops
        int s2 = tid + h * 256;
        int row = s2 >> 3, seg = s2 & 7;
        cp16(sb + OFF_A + row * RSTRIDE + seg * 16,
             g_C_h + (size_t)(m0 + row) * H_DIM + k0 + seg * 8);
    }
#pragma unroll
    for (int h = 0; h < 4; h++) {      // B: 128 rows x 8 segs = 1024 ops
        int s2 = tid + h * 256;
        int row = s2 >> 3, seg = s2 & 7;
        cp16(sb + OFF_B + row * RSTRIDE + seg * 16,
             g_W_h + (size_t)(n0 + row) * H_DIM + k0 + seg * 8);
    }
}

__global__ __launch_bounds__(256, 2) void gemm_mma_kernel(const float* __restrict__ bias,
                                                          float* __restrict__ out) {
    extern __shared__ char smem[];
    const int n_valid = g_nvalid;
    const int m0 = blockIdx.y * BM;
    const int n0 = blockIdx.x * BN;
    const int tid = threadIdx.x;

    if (m0 >= n_valid) {      // fully masked: zeros
        float4 z = make_float4(0.f, 0.f, 0.f, 0.f);
        for (int i = tid; i < BM * (BN / 4); i += 256) {
            int r = i >> 5, c4 = i & 31;
            ((float4*)(out + (size_t)(m0 + r) * D_DIM + n0))[c4] = z;
        }
        return;
    }

    const int wid = tid >> 5, lane = tid & 31;
    const int warp_m = wid >> 2;   // 0..1
    const int warp_n = wid & 3;    // 0..3
    uint32_t sb = smem_to_u32(smem);

    const uint32_t a_lane = (uint32_t)((warp_m * 64 + (lane & 15)) * RSTRIDE + (lane >> 4) * 16);
    const uint32_t b_lane = (uint32_t)((warp_n * 32 + (lane & 15)) * RSTRIDE + (lane >> 4) * 16);

    float acc[4][4][4];
#pragma unroll
    for (int i = 0; i < 4; i++)
#pragma unroll
        for (int j = 0; j < 4; j++)
#pragma unroll
            for (int k = 0; k < 4; k++) acc[i][j][k] = 0.f;

    fill_stage(sb + 0 * STAGE_BYTES, m0, n0, 0, tid); CP_COMMIT();
    fill_stage(sb + 1 * STAGE_BYTES, m0, n0, 1, tid); CP_COMMIT();

    int stage_c = 0;           // stage of chunk c (mod 3)
    for (int c = 0; c < NCHUNK; c++) {
        CP_WAIT1();
        __syncthreads();
        if (c + 2 < NCHUNK) {
            int sidx = stage_c + 2; if (sidx >= 3) sidx -= 3;
            fill_stage(sb + sidx * STAGE_BYTES, m0, n0, c + 2, tid);
        }
        CP_COMMIT();

        const uint32_t st = sb + stage_c * STAGE_BYTES;
#pragma unroll
        for (int ks = 0; ks < 4; ks++) {
            uint32_t ah[4][4], bh[4][2];
#pragma unroll
            for (int mi = 0; mi < 4; mi++) {
                uint32_t ad = st + OFF_A + a_lane + mi * (16 * RSTRIDE) + ks * 32;
                ldsm4(ad, ah[mi][0], ah[mi][1], ah[mi][2], ah[mi][3]);
            }
#pragma unroll
            for (int j = 0; j < 2; j++) {
                uint32_t bd = st + OFF_B + b_lane + j * (16 * RSTRIDE) + ks * 32;
                uint32_t r0, r1, r2, r3;
                ldsm4(bd, r0, r1, r2, r3);
                bh[2 * j][0] = r0; bh[2 * j + 1][0] = r1;
                bh[2 * j][1] = r2; bh[2 * j + 1][1] = r3;
            }
#pragma unroll
            for (int mi = 0; mi < 4; mi++)
#pragma unroll
                for (int ni = 0; ni < 4; ni++)
                    mma16816(acc[mi][ni], ah[mi], bh[ni]);
        }
        stage_c++; if (stage_c >= 3) stage_c = 0;
    }

    // Epilogue: bias + row mask
    const int r_in = lane >> 2;
    const int c2 = (lane & 3) * 2;
#pragma unroll
    for (int mi = 0; mi < 4; mi++) {
#pragma unroll
        for (int half = 0; half < 2; half++) {
            int row = m0 + warp_m * 64 + mi * 16 + r_in + half * 8;
            bool rv = row < n_valid;
            float* op = out + (size_t)row * D_DIM;
#pragma unroll
            for (int ni = 0; ni < 4; ni++) {
                int col = n0 + warp_n * 32 + ni * 8 + c2;
                float2 v;
                if (rv) {
                    float2 b2 = *(const float2*)(bias + col);
                    v.x = acc[mi][ni][half * 2 + 0] + b2.x;
                    v.y = acc[mi][ni][half * 2 + 1] + b2.y;
                } else {
                    v.x = 0.f; v.y = 0.f;
                }
                *(float2*)(op + col) = v;
            }
        }
    }
}

// ---------------------------------------------------------------------------
// Launch
// ---------------------------------------------------------------------------
extern "C" void kernel_launch(void* const* d_in, const int* in_sizes, int n_in,
                              void* d_out, int out_size) {
    const float* hidden = (const float*)d_in[0];   // [1, T, H]
    const float* logits = (const float*)d_in[1];   // [1, T, V]
    const float* W      = (const float*)d_in[2];   // [D, H]
    const float* bias   = (const float*)d_in[3];   // [D]
    float* out          = (float*)d_out;           // [1, T, D]

    cudaFuncSetAttribute(gemm_mma_kernel, cudaFuncAttributeMaxDynamicSharedMemorySize,
                         GEMM_SMEM);

    w_half_kernel<<<(D_DIM * H_DIM) / (256 * 4), 256>>>(W);
    argmax_kernel<<<T_DIM / 256, 256>>>(logits);
    segment_kernel<<<1, 1024>>>();
    mean_kernel<<<T_DIM / 8, 256>>>(hidden);
    dim3 grid(D_DIM / BN, T_DIM / BM);
    gemm_mma_kernel<<<grid, 256, GEMM_SMEM>>>(bias, out);
}